// round 2
// baseline (speedup 1.0000x reference)
#include <cuda_runtime.h>
#include <cstdint>
#include <math.h>

#define B_PTS   262144
#define HIDDEN  512
#define DIM_IN  48

// ---------------- scratch (static device arrays; no allocs) ----------------
__device__ float g_feats[(size_t)B_PTS * DIM_IN];          // 48 MB
__device__ float g_h[(size_t)B_PTS * HIDDEN];              // 512 MB (tf32-rounded)
__device__ float g_w2t[HIDDEN * HIDDEN];                   // 1 MB (tf32-rounded)

__constant__ float c_sres[16] = {16,22,30,42,58,80,111,154,212,294,406,561,776,1072,1482,2048};
__constant__ float c_tres[8]  = {8,16,32,64,128,256,512,1024};

__device__ __forceinline__ float to_tf32(float x) {
    uint32_t u;
    asm("cvt.rna.tf32.f32 %0, %1;" : "=r"(u) : "f"(x));
    return __uint_as_float(u);
}

__device__ __forceinline__ void cp16(float* s, const float* g) {
    uint32_t sa = (uint32_t)__cvta_generic_to_shared(s);
    asm volatile("cp.async.cg.shared.global [%0], [%1], 16;" :: "r"(sa), "l"(g));
}
__device__ __forceinline__ void cp_commit() { asm volatile("cp.async.commit_group;"); }
template<int N> __device__ __forceinline__ void cp_wait() {
    asm volatile("cp.async.wait_group %0;" :: "n"(N));
}

// ---------------- kernel 0: round w2 to tf32 ----------------
__global__ void prep_w2_kernel(const float* __restrict__ w2) {
    int i = blockIdx.x * 256 + threadIdx.x;
    g_w2t[i] = to_tf32(w2[i]);
}

// ---------------- kernel 1: 4D hash-grid encode ----------------
__global__ __launch_bounds__(256) void encode_kernel(
    const float4* __restrict__ xyzt,
    const int* __restrict__ smask,
    const int* __restrict__ tmask,
    const float2* __restrict__ stab,
    const float2* __restrict__ ttab)
{
    int i = blockIdx.x * 256 + threadIdx.x;
    float4 p = xyzt[i];
    float sm = smask[i] ? 1.0f : 0.0f;
    float tm = tmask[i] ? 1.0f : 0.0f;

    float out[DIM_IN];

    // spatial: 16 levels, 3D
    #pragma unroll
    for (int l = 0; l < 16; l++) {
        float r = c_sres[l];
        float px = p.x * r, py = p.y * r, pz = p.z * r;
        float fx = floorf(px), fy = floorf(py), fz = floorf(pz);
        unsigned bx = (unsigned)fx, by = (unsigned)fy, bz = (unsigned)fz;
        float wx1 = px - fx, wy1 = py - fy, wz1 = pz - fz;
        float wx0 = 1.0f - wx1, wy0 = 1.0f - wy1, wz0 = 1.0f - wz1;
        const float2* tab = stab + (size_t)l * 524288;
        unsigned hy0 = by * 2654435761u, hy1 = (by + 1u) * 2654435761u;
        unsigned hz0 = bz * 805459861u,  hz1 = (bz + 1u) * 805459861u;
        float f0 = 0.0f, f1 = 0.0f;
        #pragma unroll
        for (int cz = 0; cz < 2; cz++) {
            unsigned hz = cz ? hz1 : hz0; float wz = cz ? wz1 : wz0;
            #pragma unroll
            for (int cy = 0; cy < 2; cy++) {
                unsigned hy = cy ? hy1 : hy0; float wy = cy ? wy1 : wy0;
                #pragma unroll
                for (int cx = 0; cx < 2; cx++) {
                    unsigned idx = ((bx + (unsigned)cx) ^ hy ^ hz) & 524287u;
                    float w = (cx ? wx1 : wx0) * wy * wz;
                    float2 v = __ldg(tab + idx);
                    f0 += w * v.x;
                    f1 += w * v.y;
                }
            }
        }
        out[2 * l]     = f0 * sm;
        out[2 * l + 1] = f1 * sm;
    }

    // temporal: 8 levels, 1D
    #pragma unroll
    for (int l = 0; l < 8; l++) {
        float r = c_tres[l];
        float pt = p.w * r;
        float ft = floorf(pt);
        unsigned bt = (unsigned)ft;
        float w1v = pt - ft, w0v = 1.0f - w1v;
        const float2* tab = ttab + (size_t)l * 131072;
        unsigned i0 = bt & 131071u;
        unsigned i1 = (bt + 1u) & 131071u;
        float2 v0 = __ldg(tab + i0);
        float2 v1 = __ldg(tab + i1);
        out[32 + 2 * l]     = (w0v * v0.x + w1v * v1.x) * tm;
        out[32 + 2 * l + 1] = (w0v * v0.y + w1v * v1.y) * tm;
    }

    float4* dst = (float4*)(g_feats + (size_t)i * DIM_IN);
    #pragma unroll
    for (int q = 0; q < 12; q++)
        dst[q] = make_float4(out[4*q], out[4*q+1], out[4*q+2], out[4*q+3]);
}

// ---------------- kernel 2: GEMM1 (48->512) + LayerNorm + GELU, writes tf32 h ----
// CTA: 64 rows x 512 cols, 512 threads; thread = 8 rows x 8 (strided) cols.
#define M1_ROWS 64
#define SMEM1_FLOATS (24576 /*w1*/ + M1_ROWS*48 /*feats*/ + M1_ROWS*64*2 /*red*/ + 2*M1_ROWS)
__global__ __launch_bounds__(512, 1) void mlp1_kernel(
    const float* __restrict__ w1, const float* __restrict__ b1,
    const float* __restrict__ lng, const float* __restrict__ lnb)
{
    extern __shared__ float smem[];
    float*  w1s  = smem;                         // [48][512]
    float*  fs   = w1s + 24576;                  // [64][48]
    float2* red2 = (float2*)(fs + M1_ROWS * 48); // [64][64] (sum, sumsq)
    float*  mus  = (float*)(red2 + M1_ROWS * 64);
    float*  rss  = mus + M1_ROWS;

    int tid = threadIdx.x;

    // load w1 (96KB) and feats tile
    {
        const float4* wg = (const float4*)w1;
        float4* ws = (float4*)w1s;
        #pragma unroll
        for (int q = tid; q < 6144; q += 512) ws[q] = wg[q];
        const float4* fg = (const float4*)(g_feats + (size_t)blockIdx.x * M1_ROWS * 48);
        float4* fsv = (float4*)fs;
        for (int q = tid; q < M1_ROWS * 12; q += 512) fsv[q] = fg[q];
    }
    __syncthreads();

    int rb = tid >> 6;      // 0..7 row block (8 rows each)
    int cb = tid & 63;      // col base; cols cb + 64*j

    float c[8][8];
    #pragma unroll
    for (int i = 0; i < 8; i++)
        #pragma unroll
        for (int j = 0; j < 8; j++) c[i][j] = 0.0f;

    #pragma unroll 4
    for (int k = 0; k < 48; k++) {
        float a[8], b[8];
        #pragma unroll
        for (int i = 0; i < 8; i++) a[i] = fs[(rb * 8 + i) * 48 + k];  // broadcast
        #pragma unroll
        for (int j = 0; j < 8; j++) b[j] = w1s[k * 512 + cb + 64 * j]; // conflict-free
        #pragma unroll
        for (int i = 0; i < 8; i++)
            #pragma unroll
            for (int j = 0; j < 8; j++) c[i][j] = fmaf(a[i], b[j], c[i][j]);
    }

    float bj[8], lg[8], lb[8];
    #pragma unroll
    for (int j = 0; j < 8; j++) {
        int col = cb + 64 * j;
        bj[j] = __ldg(b1 + col);
        lg[j] = __ldg(lng + col);
        lb[j] = __ldg(lnb + col);
    }
    #pragma unroll
    for (int i = 0; i < 8; i++)
        #pragma unroll
        for (int j = 0; j < 8; j++) c[i][j] += bj[j];

    // per-row partial stats
    #pragma unroll
    for (int i = 0; i < 8; i++) {
        float s = 0.0f, s2 = 0.0f;
        #pragma unroll
        for (int j = 0; j < 8; j++) { s += c[i][j]; s2 += c[i][j] * c[i][j]; }
        red2[(rb * 8 + i) * 64 + cb] = make_float2(s, s2);
    }
    __syncthreads();

    // 16 warps reduce 4 rows each
    {
        int w = tid >> 5, lane = tid & 31;
        #pragma unroll
        for (int rr = 0; rr < 4; rr++) {
            int row = w * 4 + rr;
            float2 pa = red2[row * 64 + lane];
            float2 pb = red2[row * 64 + 32 + lane];
            float s = pa.x + pb.x, s2 = pa.y + pb.y;
            #pragma unroll
            for (int off = 16; off; off >>= 1) {
                s  += __shfl_down_sync(0xffffffffu, s, off);
                s2 += __shfl_down_sync(0xffffffffu, s2, off);
            }
            if (lane == 0) {
                float mu = s * (1.0f / 512.0f);
                float var = s2 * (1.0f / 512.0f) - mu * mu;
                mus[row] = mu;
                rss[row] = rsqrtf(var + 1e-5f);
            }
        }
    }
    __syncthreads();

    float* hout = g_h + (size_t)blockIdx.x * M1_ROWS * 512;
    #pragma unroll
    for (int i = 0; i < 8; i++) {
        int row = rb * 8 + i;
        float mu = mus[row], rs = rss[row];
        #pragma unroll
        for (int j = 0; j < 8; j++) {
            int col = cb + 64 * j;
            float y = (c[i][j] - mu) * rs * lg[j] + lb[j];
            float ge = 0.5f * y * (1.0f + erff(y * 0.70710678118654752f));
            hout[row * 512 + col] = to_tf32(ge);
        }
    }
}

// ---------------- kernel 3: GEMM2 (512x512) tf32 mma.sync ----------------
// CTA 128x64, K-chunk 32, 3-stage cp.async pipeline. 8 warps of 32x32.
#define CM 128
#define CN 64
#define CK 32
#define STG 3
#define APAD 36
#define BPAD 68
#define SMEM2_FLOATS (STG * (CM * APAD + CK * BPAD))

__global__ __launch_bounds__(256, 2) void mlp2_kernel(
    const float* __restrict__ b2, float* __restrict__ out)
{
    extern __shared__ float smem[];
    float* As = smem;                    // [STG][CM][APAD]
    float* Bs = smem + STG * CM * APAD;  // [STG][CK][BPAD]

    int tid = threadIdx.x;
    int bm = blockIdx.y, bn = blockIdx.x;
    const float* Ag = g_h + (size_t)bm * CM * 512;
    const float* Bg = g_w2t + bn * CN;

    auto loadA = [&](int kt, int s) {
        const float* src = Ag + kt * CK;
        float* dst = As + s * CM * APAD;
        #pragma unroll
        for (int i = 0; i < 4; i++) {
            int q = tid + i * 256;           // 1024 x 16B chunks
            int row = q >> 3, cc = q & 7;
            cp16(dst + row * APAD + cc * 4, src + (size_t)row * 512 + cc * 4);
        }
    };
    auto loadB = [&](int kt, int s) {
        const float* src = Bg + (size_t)kt * CK * 512;
        float* dst = Bs + s * CK * BPAD;
        #pragma unroll
        for (int i = 0; i < 2; i++) {
            int q = tid + i * 256;           // 512 x 16B chunks
            int row = q >> 4, cc = q & 15;
            cp16(dst + row * BPAD + cc * 4, src + row * 512 + cc * 4);
        }
    };

    loadA(0, 0); loadB(0, 0); cp_commit();
    loadA(1, 1); loadB(1, 1); cp_commit();

    int warp = tid >> 5, lane = tid & 31;
    int wm = warp & 3, wn = warp >> 2;
    int g = lane >> 2, t4 = lane & 3;

    float c[2][4][4] = {};

    const int NK = 512 / CK;  // 16
    for (int kt = 0; kt < NK; kt++) {
        if (kt + 2 < NK) {
            loadA(kt + 2, (kt + 2) % STG);
            loadB(kt + 2, (kt + 2) % STG);
            cp_commit();
            cp_wait<2>();
        } else if (kt + 1 < NK) {
            cp_wait<1>();
        } else {
            cp_wait<0>();
        }
        __syncthreads();

        const float* A0 = As + (kt % STG) * CM * APAD;
        const float* B0 = Bs + (kt % STG) * CK * BPAD;

        #pragma unroll
        for (int ks = 0; ks < 4; ks++) {
            uint32_t a[2][4], b[4][2];
            #pragma unroll
            for (int mf = 0; mf < 2; mf++) {
                const float* ap = A0 + (wm * 32 + mf * 16 + g) * APAD + ks * 8 + t4;
                a[mf][0] = __float_as_uint(ap[0]);
                a[mf][1] = __float_as_uint(ap[8 * APAD]);
                a[mf][2] = __float_as_uint(ap[4]);
                a[mf][3] = __float_as_uint(ap[8 * APAD + 4]);
            }
            #pragma unroll
            for (int nf = 0; nf < 4; nf++) {
                const float* bp = B0 + (ks * 8 + t4) * BPAD + wn * 32 + nf * 8 + g;
                b[nf][0] = __float_as_uint(bp[0]);
                b[nf][1] = __float_as_uint(bp[4 * BPAD]);
            }
            #pragma unroll
            for (int mf = 0; mf < 2; mf++)
                #pragma unroll
                for (int nf = 0; nf < 4; nf++) {
                    asm volatile(
                        "mma.sync.aligned.m16n8k8.row.col.f32.tf32.tf32.f32 "
                        "{%0,%1,%2,%3},{%4,%5,%6,%7},{%8,%9},{%0,%1,%2,%3};"
                        : "+f"(c[mf][nf][0]), "+f"(c[mf][nf][1]),
                          "+f"(c[mf][nf][2]), "+f"(c[mf][nf][3])
                        : "r"(a[mf][0]), "r"(a[mf][1]), "r"(a[mf][2]), "r"(a[mf][3]),
                          "r"(b[nf][0]), "r"(b[nf][1]));
                }
        }
        __syncthreads();
    }

    // epilogue: + b2, store fp32
    #pragma unroll
    for (int mf = 0; mf < 2; mf++) {
        #pragma unroll
        for (int nf = 0; nf < 4; nf++) {
            int row = bm * CM + wm * 32 + mf * 16 + g;
            int col = bn * CN + wn * 32 + nf * 8 + 2 * t4;
            float2 bb = *(const float2*)(b2 + col);
            float2 v0 = make_float2(c[mf][nf][0] + bb.x, c[mf][nf][1] + bb.y);
            float2 v1 = make_float2(c[mf][nf][2] + bb.x, c[mf][nf][3] + bb.y);
            *(float2*)(out + (size_t)row * 512 + col) = v0;
            *(float2*)(out + (size_t)(row + 8) * 512 + col) = v1;
        }
    }
}

// ---------------- launch ----------------
extern "C" void kernel_launch(void* const* d_in, const int* in_sizes, int n_in,
                              void* d_out, int out_size)
{
    const float* xyzt  = (const float*)d_in[0];
    const int*   smask = (const int*)d_in[1];
    const int*   tmask = (const int*)d_in[2];
    const float* stab  = (const float*)d_in[3];
    const float* ttab  = (const float*)d_in[4];
    const float* w1    = (const float*)d_in[5];
    const float* b1    = (const float*)d_in[6];
    const float* lng   = (const float*)d_in[7];
    const float* lnb   = (const float*)d_in[8];
    const float* w2    = (const float*)d_in[9];
    const float* b2    = (const float*)d_in[10];
    float*       out   = (float*)d_out;

    cudaFuncSetAttribute(mlp1_kernel, cudaFuncAttributeMaxDynamicSharedMemorySize,
                         SMEM1_FLOATS * 4);
    cudaFuncSetAttribute(mlp2_kernel, cudaFuncAttributeMaxDynamicSharedMemorySize,
                         SMEM2_FLOATS * 4);

    prep_w2_kernel<<<(HIDDEN * HIDDEN) / 256, 256>>>(w2);
    encode_kernel<<<B_PTS / 256, 256>>>((const float4*)xyzt, smask, tmask,
                                        (const float2*)stab, (const float2*)ttab);
    mlp1_kernel<<<B_PTS / M1_ROWS, 512, SMEM1_FLOATS * 4>>>(w1, b1, lng, lnb);
    dim3 g2(HIDDEN / CN, B_PTS / CM);
    mlp2_kernel<<<g2, 256, SMEM2_FLOATS * 4>>>(b2, out);
}

// round 6
// speedup vs baseline: 1.7030x; 1.7030x over previous
#include <cuda_runtime.h>
#include <cuda_fp16.h>
#include <cstdint>
#include <math.h>

#define B_PTS   262144
#define HIDDEN  512
#define DIM_IN  48

// ---------------- scratch (static device arrays; no allocs) ----------------
__device__ float  g_feats[(size_t)B_PTS * DIM_IN];          // 48 MB
__device__ __half g_h[(size_t)B_PTS * HIDDEN];              // 256 MB fp16
__device__ __half g_w2h[HIDDEN * HIDDEN];                   // 512 KB, [N][K] K-major fp16

__constant__ float c_sres[16] = {16,22,30,42,58,80,111,154,212,294,406,561,776,1072,1482,2048};
__constant__ float c_tres[8]  = {8,16,32,64,128,256,512,1024};

__device__ __forceinline__ void cp16(void* s, const void* g) {
    uint32_t sa = (uint32_t)__cvta_generic_to_shared(s);
    asm volatile("cp.async.cg.shared.global [%0], [%1], 16;" :: "r"(sa), "l"(g));
}
__device__ __forceinline__ void cp_commit() { asm volatile("cp.async.commit_group;"); }
template<int N> __device__ __forceinline__ void cp_wait() {
    asm volatile("cp.async.wait_group %0;" :: "n"(N));
}
__device__ __forceinline__ uint32_t smem_u32(const void* p) {
    return (uint32_t)__cvta_generic_to_shared(p);
}
__device__ __forceinline__ void ldsm_x4(uint32_t& r0, uint32_t& r1, uint32_t& r2, uint32_t& r3,
                                        uint32_t addr) {
    asm volatile("ldmatrix.sync.aligned.m8n8.x4.shared.b16 {%0,%1,%2,%3}, [%4];"
                 : "=r"(r0), "=r"(r1), "=r"(r2), "=r"(r3) : "r"(addr));
}
__device__ __forceinline__ void mma16816(float* c, const uint32_t* a, uint32_t b0, uint32_t b1) {
    asm volatile(
        "mma.sync.aligned.m16n8k16.row.col.f32.f16.f16.f32 "
        "{%0,%1,%2,%3},{%4,%5,%6,%7},{%8,%9},{%0,%1,%2,%3};"
        : "+f"(c[0]), "+f"(c[1]), "+f"(c[2]), "+f"(c[3])
        : "r"(a[0]), "r"(a[1]), "r"(a[2]), "r"(a[3]), "r"(b0), "r"(b1));
}

// ---------------- kernel 0: transpose + fp16-round w2 -> g_w2h[N][K] ----------------
__global__ void prep_w2_kernel(const float* __restrict__ w2) {
    __shared__ float tile[32][33];
    int x = blockIdx.x * 32 + threadIdx.x;   // n
    int y = blockIdx.y * 32 + threadIdx.y;   // k
    tile[threadIdx.y][threadIdx.x] = w2[y * 512 + x];
    __syncthreads();
    int ko = blockIdx.y * 32 + threadIdx.x;  // k (contiguous out)
    int no = blockIdx.x * 32 + threadIdx.y;  // n
    g_w2h[no * 512 + ko] = __float2half_rn(tile[threadIdx.x][threadIdx.y]);
}

// ---------------- kernel 1: 4D hash-grid encode ----------------
__global__ __launch_bounds__(256) void encode_kernel(
    const float4* __restrict__ xyzt,
    const int* __restrict__ smask,
    const int* __restrict__ tmask,
    const float2* __restrict__ stab,
    const float2* __restrict__ ttab)
{
    int i = blockIdx.x * 256 + threadIdx.x;
    float4 p = xyzt[i];
    float sm = smask[i] ? 1.0f : 0.0f;
    float tm = tmask[i] ? 1.0f : 0.0f;

    float out[DIM_IN];

    #pragma unroll
    for (int l = 0; l < 16; l++) {
        float r = c_sres[l];
        float px = p.x * r, py = p.y * r, pz = p.z * r;
        float fx = floorf(px), fy = floorf(py), fz = floorf(pz);
        unsigned bx = (unsigned)fx, by = (unsigned)fy, bz = (unsigned)fz;
        float wx1 = px - fx, wy1 = py - fy, wz1 = pz - fz;
        float wx0 = 1.0f - wx1, wy0 = 1.0f - wy1, wz0 = 1.0f - wz1;
        const float2* tab = stab + (size_t)l * 524288;
        unsigned hy0 = by * 2654435761u, hy1 = (by + 1u) * 2654435761u;
        unsigned hz0 = bz * 805459861u,  hz1 = (bz + 1u) * 805459861u;
        float f0 = 0.0f, f1 = 0.0f;
        #pragma unroll
        for (int cz = 0; cz < 2; cz++) {
            unsigned hz = cz ? hz1 : hz0; float wz = cz ? wz1 : wz0;
            #pragma unroll
            for (int cy = 0; cy < 2; cy++) {
                unsigned hy = cy ? hy1 : hy0; float wy = cy ? wy1 : wy0;
                #pragma unroll
                for (int cx = 0; cx < 2; cx++) {
                    unsigned idx = ((bx + (unsigned)cx) ^ hy ^ hz) & 524287u;
                    float w = (cx ? wx1 : wx0) * wy * wz;
                    float2 v = __ldg(tab + idx);
                    f0 += w * v.x;
                    f1 += w * v.y;
                }
            }
        }
        out[2 * l]     = f0 * sm;
        out[2 * l + 1] = f1 * sm;
    }

    #pragma unroll
    for (int l = 0; l < 8; l++) {
        float r = c_tres[l];
        float pt = p.w * r;
        float ft = floorf(pt);
        unsigned bt = (unsigned)ft;
        float w1v = pt - ft, w0v = 1.0f - w1v;
        const float2* tab = ttab + (size_t)l * 131072;
        float2 v0 = __ldg(tab + (bt & 131071u));
        float2 v1 = __ldg(tab + ((bt + 1u) & 131071u));
        out[32 + 2 * l]     = (w0v * v0.x + w1v * v1.x) * tm;
        out[32 + 2 * l + 1] = (w0v * v0.y + w1v * v1.y) * tm;
    }

    float4* dst = (float4*)(g_feats + (size_t)i * DIM_IN);
    #pragma unroll
    for (int q = 0; q < 12; q++)
        dst[q] = make_float4(out[4*q], out[4*q+1], out[4*q+2], out[4*q+3]);
}

// ---------------- kernel 2: GEMM1 (48->512) + LayerNorm + GELU -> fp16 h ----------
#define M1_ROWS 64
#define SMEM1_FLOATS (24576 + M1_ROWS*48 + M1_ROWS*64*2 + 2*M1_ROWS)
__global__ __launch_bounds__(512, 1) void mlp1_kernel(
    const float* __restrict__ w1, const float* __restrict__ b1,
    const float* __restrict__ lng, const float* __restrict__ lnb)
{
    extern __shared__ float smem[];
    float*  w1s  = smem;                         // [48][512]
    float*  fs   = w1s + 24576;                  // [64][48]
    float2* red2 = (float2*)(fs + M1_ROWS * 48); // [64][64]
    float*  mus  = (float*)(red2 + M1_ROWS * 64);
    float*  rss  = mus + M1_ROWS;

    int tid = threadIdx.x;
    {
        const float4* wg = (const float4*)w1;
        float4* ws = (float4*)w1s;
        #pragma unroll
        for (int q = tid; q < 6144; q += 512) ws[q] = wg[q];
        const float4* fg = (const float4*)(g_feats + (size_t)blockIdx.x * M1_ROWS * 48);
        float4* fsv = (float4*)fs;
        for (int q = tid; q < M1_ROWS * 12; q += 512) fsv[q] = fg[q];
    }
    __syncthreads();

    int rb = tid >> 6, cb = tid & 63;
    float c[8][8];
    #pragma unroll
    for (int i = 0; i < 8; i++)
        #pragma unroll
        for (int j = 0; j < 8; j++) c[i][j] = 0.0f;

    #pragma unroll 4
    for (int k = 0; k < 48; k++) {
        float a[8], b[8];
        #pragma unroll
        for (int i = 0; i < 8; i++) a[i] = fs[(rb * 8 + i) * 48 + k];
        #pragma unroll
        for (int j = 0; j < 8; j++) b[j] = w1s[k * 512 + cb + 64 * j];
        #pragma unroll
        for (int i = 0; i < 8; i++)
            #pragma unroll
            for (int j = 0; j < 8; j++) c[i][j] = fmaf(a[i], b[j], c[i][j]);
    }

    float bj[8], lg[8], lb[8];
    #pragma unroll
    for (int j = 0; j < 8; j++) {
        int col = cb + 64 * j;
        bj[j] = __ldg(b1 + col);
        lg[j] = __ldg(lng + col);
        lb[j] = __ldg(lnb + col);
    }
    #pragma unroll
    for (int i = 0; i < 8; i++)
        #pragma unroll
        for (int j = 0; j < 8; j++) c[i][j] += bj[j];

    #pragma unroll
    for (int i = 0; i < 8; i++) {
        float s = 0.0f, s2 = 0.0f;
        #pragma unroll
        for (int j = 0; j < 8; j++) { s += c[i][j]; s2 += c[i][j] * c[i][j]; }
        red2[(rb * 8 + i) * 64 + cb] = make_float2(s, s2);
    }
    __syncthreads();

    {
        int w = tid >> 5, lane = tid & 31;
        #pragma unroll
        for (int rr = 0; rr < 4; rr++) {
            int row = w * 4 + rr;
            float2 pa = red2[row * 64 + lane];
            float2 pb = red2[row * 64 + 32 + lane];
            float s = pa.x + pb.x, s2 = pa.y + pb.y;
            #pragma unroll
            for (int off = 16; off; off >>= 1) {
                s  += __shfl_down_sync(0xffffffffu, s, off);
                s2 += __shfl_down_sync(0xffffffffu, s2, off);
            }
            if (lane == 0) {
                float mu = s * (1.0f / 512.0f);
                float var = s2 * (1.0f / 512.0f) - mu * mu;
                mus[row] = mu;
                rss[row] = rsqrtf(var + 1e-5f);
            }
        }
    }
    __syncthreads();

    __half* hout = g_h + (size_t)blockIdx.x * M1_ROWS * 512;
    #pragma unroll
    for (int i = 0; i < 8; i++) {
        int row = rb * 8 + i;
        float mu = mus[row], rs = rss[row];
        #pragma unroll
        for (int j = 0; j < 8; j++) {
            int col = cb + 64 * j;
            float y = (c[i][j] - mu) * rs * lg[j] + lb[j];
            float ge = 0.5f * y * (1.0f + erff(y * 0.70710678118654752f));
            hout[row * 512 + col] = __float2half_rn(ge);
        }
    }
}

// ---------------- kernel 3: GEMM2 (512x512) fp16 mma.sync + ldmatrix ----------------
// CTA 128x128, 8 warps of 32x64. CK=32 halves, 3-stage cp.async.
// smem stride 40 halves (80B = 5x16B, gcd(5,8)=1 -> ldmatrix conflict-free).
#define AST 40
#define STAGE_HALVES (2 * 128 * AST)              // A block + B block
#define STAGE_BYTES  (STAGE_HALVES * 2)           // 20480
#define SMEM2_BYTES  (3 * STAGE_BYTES)            // 61440

__global__ __launch_bounds__(256, 2) void mlp2_kernel(
    const float* __restrict__ b2, float* __restrict__ out)
{
    extern __shared__ __half sm2[];
    uint32_t smem_base = smem_u32(sm2);

    int tid = threadIdx.x;
    int wid = tid >> 5, lane = tid & 31;
    int bn = blockIdx.x, bm = blockIdx.y;
    const __half* Ag = g_h   + (size_t)bm * 128 * 512;
    const __half* Bg = g_w2h + (size_t)bn * 128 * 512;

    auto load = [&](int kt, int s) {
        __half* dstA = sm2 + (size_t)s * STAGE_HALVES;
        #pragma unroll
        for (int i = 0; i < 2; i++) {
            int q = tid + i * 256;             // 512 x 16B
            int r = q >> 2, cc = q & 3;
            cp16(dstA + r * AST + cc * 8, Ag + (size_t)r * 512 + kt * 32 + cc * 8);
        }
        __half* dstB = dstA + 128 * AST;
        #pragma unroll
        for (int i = 0; i < 2; i++) {
            int q = tid + i * 256;
            int r = q >> 2, cc = q & 3;
            cp16(dstB + r * AST + cc * 8, Bg + (size_t)r * 512 + kt * 32 + cc * 8);
        }
    };

    load(0, 0); cp_commit();
    load(1, 1); cp_commit();

    int wm = wid & 3, wn = wid >> 2;
    int g = lane >> 2, t4 = lane & 3;
    int lrow = lane & 15, lcol = (lane >> 4) * 8;

    float c[2][8][4] = {};

    for (int kt = 0; kt < 16; kt++) {
        if (kt + 2 < 16) { load(kt + 2, (kt + 2) % 3); cp_commit(); cp_wait<2>(); }
        else if (kt + 1 < 16) cp_wait<1>();
        else cp_wait<0>();
        __syncthreads();

        uint32_t base = smem_base + (uint32_t)((kt % 3) * STAGE_BYTES);

        #pragma unroll
        for (int ks = 0; ks < 2; ks++) {
            uint32_t a[2][4];
            #pragma unroll
            for (int mf = 0; mf < 2; mf++) {
                uint32_t ad = base + ((wm * 32 + mf * 16 + lrow) * AST + ks * 16 + lcol) * 2;
                ldsm_x4(a[mf][0], a[mf][1], a[mf][2], a[mf][3], ad);
            }
            uint32_t b[4][4];
            #pragma unroll
            for (int nq = 0; nq < 4; nq++) {
                uint32_t bd = base + 128 * AST * 2 +
                              ((wn * 64 + nq * 16 + lrow) * AST + ks * 16 + lcol) * 2;
                ldsm_x4(b[nq][0], b[nq][1], b[nq][2], b[nq][3], bd);
            }
            #pragma unroll
            for (int mf = 0; mf < 2; mf++)
                #pragma unroll
                for (int nq = 0; nq < 4; nq++) {
                    mma16816(c[mf][nq * 2 + 0], a[mf], b[nq][0], b[nq][2]);
                    mma16816(c[mf][nq * 2 + 1], a[mf], b[nq][1], b[nq][3]);
                }
        }
        __syncthreads();
    }

    // epilogue: + b2, fp32 out
    #pragma unroll
    for (int mf = 0; mf < 2; mf++) {
        #pragma unroll
        for (int nf = 0; nf < 8; nf++) {
            int row = bm * 128 + wm * 32 + mf * 16 + g;
            int col = bn * 128 + wn * 64 + nf * 8 + 2 * t4;
            float2 bb = *(const float2*)(b2 + col);
            float2 v0 = make_float2(c[mf][nf][0] + bb.x, c[mf][nf][1] + bb.y);
            float2 v1 = make_float2(c[mf][nf][2] + bb.x, c[mf][nf][3] + bb.y);
            *(float2*)(out + (size_t)row * 512 + col) = v0;
            *(float2*)(out + (size_t)(row + 8) * 512 + col) = v1;
        }
    }
}

// ---------------- launch ----------------
extern "C" void kernel_launch(void* const* d_in, const int* in_sizes, int n_in,
                              void* d_out, int out_size)
{
    const float* xyzt  = (const float*)d_in[0];
    const int*   smask = (const int*)d_in[1];
    const int*   tmask = (const int*)d_in[2];
    const float* stab  = (const float*)d_in[3];
    const float* ttab  = (const float*)d_in[4];
    const float* w1    = (const float*)d_in[5];
    const float* b1    = (const float*)d_in[6];
    const float* lng   = (const float*)d_in[7];
    const float* lnb   = (const float*)d_in[8];
    const float* w2    = (const float*)d_in[9];
    const float* b2    = (const float*)d_in[10];
    float*       out   = (float*)d_out;

    cudaFuncSetAttribute(mlp1_kernel, cudaFuncAttributeMaxDynamicSharedMemorySize,
                         SMEM1_FLOATS * 4);
    cudaFuncSetAttribute(mlp2_kernel, cudaFuncAttributeMaxDynamicSharedMemorySize,
                         SMEM2_BYTES);

    dim3 tb(32, 32);
    dim3 tg(16, 16);
    prep_w2_kernel<<<tg, tb>>>(w2);
    encode_kernel<<<B_PTS / 256, 256>>>((const float4*)xyzt, smask, tmask,
                                        (const float2*)stab, (const float2*)ttab);
    mlp1_kernel<<<B_PTS / M1_ROWS, 512, SMEM1_FLOATS * 4>>>(w1, b1, lng, lnb);
    dim3 g2(HIDDEN / 128, B_PTS / 128);     // bn fastest -> A slab L2 reuse
    mlp2_kernel<<<g2, 256, SMEM2_BYTES>>>(b2, out);
}

// round 8
// speedup vs baseline: 2.2033x; 1.2938x over previous
#include <cuda_runtime.h>
#include <cuda_fp16.h>
#include <cstdint>
#include <math.h>

#define B_PTS   262144
#define HIDDEN  512
#define DIM_IN  48

// ---------------- scratch (static device arrays; no allocs) ----------------
__device__ __half g_feats[(size_t)B_PTS * DIM_IN];          // 24 MB fp16
__device__ __half g_h[(size_t)B_PTS * HIDDEN];              // 256 MB fp16
__device__ __half g_w2h[HIDDEN * HIDDEN];                   // [N][K] K-major fp16
__device__ __half g_w1h[HIDDEN * DIM_IN];                   // [N=512][K=48] fp16

__constant__ float c_sres[16] = {16,22,30,42,58,80,111,154,212,294,406,561,776,1072,1482,2048};
__constant__ float c_tres[8]  = {8,16,32,64,128,256,512,1024};

__device__ __forceinline__ void cp16(void* s, const void* g) {
    uint32_t sa = (uint32_t)__cvta_generic_to_shared(s);
    asm volatile("cp.async.cg.shared.global [%0], [%1], 16;" :: "r"(sa), "l"(g));
}
__device__ __forceinline__ void cp_commit() { asm volatile("cp.async.commit_group;"); }
template<int N> __device__ __forceinline__ void cp_wait() {
    asm volatile("cp.async.wait_group %0;" :: "n"(N));
}
__device__ __forceinline__ uint32_t smem_u32(const void* p) {
    return (uint32_t)__cvta_generic_to_shared(p);
}
__device__ __forceinline__ void ldsm_x4(uint32_t& r0, uint32_t& r1, uint32_t& r2, uint32_t& r3,
                                        uint32_t addr) {
    asm volatile("ldmatrix.sync.aligned.m8n8.x4.shared.b16 {%0,%1,%2,%3}, [%4];"
                 : "=r"(r0), "=r"(r1), "=r"(r2), "=r"(r3) : "r"(addr));
}
__device__ __forceinline__ void mma16816(float* c, const uint32_t* a, uint32_t b0, uint32_t b1) {
    asm volatile(
        "mma.sync.aligned.m16n8k16.row.col.f32.f16.f16.f32 "
        "{%0,%1,%2,%3},{%4,%5,%6,%7},{%8,%9},{%0,%1,%2,%3};"
        : "+f"(c[0]), "+f"(c[1]), "+f"(c[2]), "+f"(c[3])
        : "r"(a[0]), "r"(a[1]), "r"(a[2]), "r"(a[3]), "r"(b0), "r"(b1));
}
__device__ __forceinline__ float gelu_exact(float y) {
    return 0.5f * y * (1.0f + erff(y * 0.70710678118654752f));
}

// ---------------- kernel 0a: transpose + fp16-round w2 -> g_w2h[N][K] ----------------
__global__ void prep_w2_kernel(const float* __restrict__ w2) {
    __shared__ float tile[32][33];
    int x = blockIdx.x * 32 + threadIdx.x;   // n
    int y = blockIdx.y * 32 + threadIdx.y;   // k
    tile[threadIdx.y][threadIdx.x] = w2[y * 512 + x];
    __syncthreads();
    int ko = blockIdx.y * 32 + threadIdx.x;  // k
    int no = blockIdx.x * 32 + threadIdx.y;  // n
    g_w2h[no * 512 + ko] = __float2half_rn(tile[threadIdx.x][threadIdx.y]);
}

// ---------------- kernel 0b: transpose + fp16-round w1 -> g_w1h[N=512][K=48] ---------
__global__ void prep_w1_kernel(const float* __restrict__ w1) {
    int i = blockIdx.x * 256 + threadIdx.x;   // i over 512*48
    int n = i / 48, k = i % 48;
    g_w1h[i] = __float2half_rn(w1[k * 512 + n]);
}

// ---------------- kernel 1: 4D hash-grid encode -> fp16 feats ----------------
__global__ __launch_bounds__(256) void encode_kernel(
    const float4* __restrict__ xyzt,
    const int* __restrict__ smask,
    const int* __restrict__ tmask,
    const float2* __restrict__ stab,
    const float2* __restrict__ ttab)
{
    int i = blockIdx.x * 256 + threadIdx.x;
    float4 p = xyzt[i];
    float sm = smask[i] ? 1.0f : 0.0f;
    float tm = tmask[i] ? 1.0f : 0.0f;

    float out[DIM_IN];

    #pragma unroll
    for (int l = 0; l < 16; l++) {
        float r = c_sres[l];
        float px = p.x * r, py = p.y * r, pz = p.z * r;
        float fx = floorf(px), fy = floorf(py), fz = floorf(pz);
        unsigned bx = (unsigned)fx, by = (unsigned)fy, bz = (unsigned)fz;
        float wx1 = px - fx, wy1 = py - fy, wz1 = pz - fz;
        float wx0 = 1.0f - wx1, wy0 = 1.0f - wy1, wz0 = 1.0f - wz1;
        const float2* tab = stab + (size_t)l * 524288;
        unsigned hy0 = by * 2654435761u, hy1 = (by + 1u) * 2654435761u;
        unsigned hz0 = bz * 805459861u,  hz1 = (bz + 1u) * 805459861u;
        float f0 = 0.0f, f1 = 0.0f;
        #pragma unroll
        for (int cz = 0; cz < 2; cz++) {
            unsigned hz = cz ? hz1 : hz0; float wz = cz ? wz1 : wz0;
            #pragma unroll
            for (int cy = 0; cy < 2; cy++) {
                unsigned hy = cy ? hy1 : hy0; float wy = cy ? wy1 : wy0;
                #pragma unroll
                for (int cx = 0; cx < 2; cx++) {
                    unsigned idx = ((bx + (unsigned)cx) ^ hy ^ hz) & 524287u;
                    float w = (cx ? wx1 : wx0) * wy * wz;
                    float2 v = __ldg(tab + idx);
                    f0 += w * v.x;
                    f1 += w * v.y;
                }
            }
        }
        out[2 * l]     = f0 * sm;
        out[2 * l + 1] = f1 * sm;
    }

    #pragma unroll
    for (int l = 0; l < 8; l++) {
        float r = c_tres[l];
        float pt = p.w * r;
        float ft = floorf(pt);
        unsigned bt = (unsigned)ft;
        float w1v = pt - ft, w0v = 1.0f - w1v;
        const float2* tab = ttab + (size_t)l * 131072;
        float2 v0 = __ldg(tab + (bt & 131071u));
        float2 v1 = __ldg(tab + ((bt + 1u) & 131071u));
        out[32 + 2 * l]     = (w0v * v0.x + w1v * v1.x) * tm;
        out[32 + 2 * l + 1] = (w0v * v0.y + w1v * v1.y) * tm;
    }

    // pack to fp16, 6 x 16B stores
    uint32_t w[24];
    #pragma unroll
    for (int j = 0; j < 24; j++) {
        __half2 h2 = __floats2half2_rn(out[2*j], out[2*j+1]);
        w[j] = *(uint32_t*)&h2;
    }
    uint4* dst = (uint4*)(g_feats + (size_t)i * DIM_IN);
    #pragma unroll
    for (int q = 0; q < 6; q++)
        dst[q] = make_uint4(w[4*q], w[4*q+1], w[4*q+2], w[4*q+3]);
}

// ---------------- kernel 2: GEMM1 (48->512) fp16 mma + LN + GELU -> fp16 h ----------
// CTA: 32 rows x 512 cols, 8 warps (one per 64-col slab). K=48 = 3 ksteps.
// smem row stride 56 halves (112B -> ldmatrix conflict-free).
// hstage overlays w1s (dead after mainloop); w1s region = 57344B >= 33280B needed.
#define KP 56
#define M1_SMEM_BYTES (512*KP*2 /*w1*/ + 32*KP*2 /*feats*/ + 32*8*8 /*red*/ + 256 /*mus+rss*/)
__global__ __launch_bounds__(256, 1) void mlp1_kernel(
    const float* __restrict__ b1,
    const float* __restrict__ lng, const float* __restrict__ lnb)
{
    extern __shared__ __align__(16) char sm1[];
    __half* w1s = (__half*)sm1;               // [512][KP]
    __half* fs  = w1s + 512 * KP;             // [32][KP]
    float2* red = (float2*)(fs + 32 * KP);    // [32][8]
    float*  mus = (float*)(red + 32 * 8);
    float*  rss = mus + 32;
    __half* hstage = (__half*)sm1;            // overlay w1s after mainloop: [32][520]

    int tid = threadIdx.x;
    int wid = tid >> 5, lane = tid & 31;

    // load w1h (512 rows x 6 chunks) and feats (32 rows x 6 chunks)
    for (int q = tid; q < 3072; q += 256) {
        int r = q / 6, cc = q % 6;
        cp16(w1s + r * KP + cc * 8, g_w1h + r * 48 + cc * 8);
    }
    {
        const __half* fg = g_feats + (size_t)blockIdx.x * 32 * 48;
        if (tid < 192) {
            int r = tid / 6, cc = tid % 6;
            cp16(fs + r * KP + cc * 8, fg + r * 48 + cc * 8);
        }
    }
    cp_commit(); cp_wait<0>();
    __syncthreads();

    int g = lane >> 2, t4 = lane & 3;
    int lrow = lane & 15, lcol = (lane >> 4) * 8;
    uint32_t fsb = smem_u32(fs), wsb = smem_u32(w1s);

    float c[2][8][4] = {};

    #pragma unroll
    for (int ks = 0; ks < 3; ks++) {
        uint32_t a[2][4];
        #pragma unroll
        for (int mf = 0; mf < 2; mf++) {
            uint32_t ad = fsb + (uint32_t)(((mf * 16 + lrow) * KP + ks * 16 + lcol) * 2);
            ldsm_x4(a[mf][0], a[mf][1], a[mf][2], a[mf][3], ad);
        }
        uint32_t b[4][4];
        #pragma unroll
        for (int nq = 0; nq < 4; nq++) {
            uint32_t bd = wsb + (uint32_t)(((wid * 64 + nq * 16 + lrow) * KP + ks * 16 + lcol) * 2);
            ldsm_x4(b[nq][0], b[nq][1], b[nq][2], b[nq][3], bd);
        }
        #pragma unroll
        for (int mf = 0; mf < 2; mf++)
            #pragma unroll
            for (int nq = 0; nq < 4; nq++) {
                mma16816(c[mf][nq * 2 + 0], a[mf], b[nq][0], b[nq][2]);
                mma16816(c[mf][nq * 2 + 1], a[mf], b[nq][1], b[nq][3]);
            }
    }

    // + b1
    #pragma unroll
    for (int nf = 0; nf < 8; nf++) {
        int col = wid * 64 + nf * 8 + 2 * t4;
        float2 bbv = *(const float2*)(b1 + col);
        #pragma unroll
        for (int mf = 0; mf < 2; mf++) {
            c[mf][nf][0] += bbv.x; c[mf][nf][1] += bbv.y;
            c[mf][nf][2] += bbv.x; c[mf][nf][3] += bbv.y;
        }
    }

    // LN stats: 4 row-slots per thread (rows g, g+8, g+16, g+24)
    {
        float s[4] = {0,0,0,0}, s2[4] = {0,0,0,0};
        #pragma unroll
        for (int nf = 0; nf < 8; nf++) {
            #pragma unroll
            for (int mf = 0; mf < 2; mf++) {
                float v0 = c[mf][nf][0], v1 = c[mf][nf][1];
                float v2 = c[mf][nf][2], v3 = c[mf][nf][3];
                s[mf*2+0] += v0 + v1;  s2[mf*2+0] += v0*v0 + v1*v1;
                s[mf*2+1] += v2 + v3;  s2[mf*2+1] += v2*v2 + v3*v3;
            }
        }
        #pragma unroll
        for (int r = 0; r < 4; r++) {
            #pragma unroll
            for (int off = 1; off < 4; off <<= 1) {
                s[r]  += __shfl_xor_sync(0xffffffffu, s[r],  off);
                s2[r] += __shfl_xor_sync(0xffffffffu, s2[r], off);
            }
        }
        if (t4 == 0) {
            red[(g     ) * 8 + wid] = make_float2(s[0], s2[0]);
            red[(g + 8 ) * 8 + wid] = make_float2(s[1], s2[1]);
            red[(g + 16) * 8 + wid] = make_float2(s[2], s2[2]);
            red[(g + 24) * 8 + wid] = make_float2(s[3], s2[3]);
        }
    }
    __syncthreads();
    if (tid < 32) {
        float s = 0.0f, s2 = 0.0f;
        #pragma unroll
        for (int j = 0; j < 8; j++) {
            float2 v = red[tid * 8 + j];
            s += v.x; s2 += v.y;
        }
        float mu = s * (1.0f / 512.0f);
        float var = s2 * (1.0f / 512.0f) - mu * mu;
        mus[tid] = mu;
        rss[tid] = rsqrtf(var + 1e-5f);
    }
    __syncthreads();   // also: all ldmatrix reads of w1s are done -> safe to overlay

    // epilogue: LN + GELU -> hstage (smem), then coalesced copy out
    {
        float mu[4], rs[4];
        #pragma unroll
        for (int r = 0; r < 4; r++) { mu[r] = mus[g + 8*r]; rs[r] = rss[g + 8*r]; }
        #pragma unroll
        for (int nf = 0; nf < 8; nf++) {
            int col = wid * 64 + nf * 8 + 2 * t4;
            float2 lgv = *(const float2*)(lng + col);
            float2 lbv = *(const float2*)(lnb + col);
            #pragma unroll
            for (int mf = 0; mf < 2; mf++) {
                int r0 = mf * 2, r1 = mf * 2 + 1;
                float y0 = (c[mf][nf][0] - mu[r0]) * rs[r0] * lgv.x + lbv.x;
                float y1 = (c[mf][nf][1] - mu[r0]) * rs[r0] * lgv.y + lbv.y;
                float y2 = (c[mf][nf][2] - mu[r1]) * rs[r1] * lgv.x + lbv.x;
                float y3 = (c[mf][nf][3] - mu[r1]) * rs[r1] * lgv.y + lbv.y;
                __half2 h0 = __floats2half2_rn(gelu_exact(y0), gelu_exact(y1));
                __half2 h1 = __floats2half2_rn(gelu_exact(y2), gelu_exact(y3));
                *(__half2*)(hstage + (mf * 16 + g) * 520 + col)     = h0;
                *(__half2*)(hstage + (mf * 16 + g + 8) * 520 + col) = h1;
            }
        }
    }
    __syncthreads();
    {
        uint4* hout = (uint4*)(g_h + (size_t)blockIdx.x * 32 * 512);
        #pragma unroll
        for (int i = 0; i < 8; i++) {
            int q = tid + i * 256;             // 2048 x 16B
            int r = q >> 6, cc = q & 63;
            hout[q] = *(uint4*)(hstage + r * 520 + cc * 8);
        }
    }
}

// ---------------- kernel 3: GEMM2 (512x512) fp16 mma.sync + ldmatrix ----------------
#define AST 40
#define STAGE_HALVES (2 * 128 * AST)
#define STAGE_BYTES  (STAGE_HALVES * 2)
#define SMEM2_BYTES  (3 * STAGE_BYTES)

__global__ __launch_bounds__(256, 2) void mlp2_kernel(
    const float* __restrict__ b2, float* __restrict__ out)
{
    extern __shared__ __half sm2[];
    uint32_t smem_base = smem_u32(sm2);

    int tid = threadIdx.x;
    int wid = tid >> 5, lane = tid & 31;
    int bn = blockIdx.x, bm = blockIdx.y;
    const __half* Ag = g_h   + (size_t)bm * 128 * 512;
    const __half* Bg = g_w2h + (size_t)bn * 128 * 512;

    auto load = [&](int kt, int s) {
        __half* dstA = sm2 + (size_t)s * STAGE_HALVES;
        #pragma unroll
        for (int i = 0; i < 2; i++) {
            int q = tid + i * 256;
            int r = q >> 2, cc = q & 3;
            cp16(dstA + r * AST + cc * 8, Ag + (size_t)r * 512 + kt * 32 + cc * 8);
        }
        __half* dstB = dstA + 128 * AST;
        #pragma unroll
        for (int i = 0; i < 2; i++) {
            int q = tid + i * 256;
            int r = q >> 2, cc = q & 3;
            cp16(dstB + r * AST + cc * 8, Bg + (size_t)r * 512 + kt * 32 + cc * 8);
        }
    };

    load(0, 0); cp_commit();
    load(1, 1); cp_commit();

    int wm = wid & 3, wn = wid >> 2;
    int g = lane >> 2, t4 = lane & 3;
    int lrow = lane & 15, lcol = (lane >> 4) * 8;

    float c[2][8][4] = {};

    for (int kt = 0; kt < 16; kt++) {
        if (kt + 2 < 16) { load(kt + 2, (kt + 2) % 3); cp_commit(); cp_wait<2>(); }
        else if (kt + 1 < 16) cp_wait<1>();
        else cp_wait<0>();
        __syncthreads();

        uint32_t base = smem_base + (uint32_t)((kt % 3) * STAGE_BYTES);

        #pragma unroll
        for (int ks = 0; ks < 2; ks++) {
            uint32_t a[2][4];
            #pragma unroll
            for (int mf = 0; mf < 2; mf++) {
                uint32_t ad = base + ((wm * 32 + mf * 16 + lrow) * AST + ks * 16 + lcol) * 2;
                ldsm_x4(a[mf][0], a[mf][1], a[mf][2], a[mf][3], ad);
            }
            uint32_t b[4][4];
            #pragma unroll
            for (int nq = 0; nq < 4; nq++) {
                uint32_t bd = base + 128 * AST * 2 +
                              ((wn * 64 + nq * 16 + lrow) * AST + ks * 16 + lcol) * 2;
                ldsm_x4(b[nq][0], b[nq][1], b[nq][2], b[nq][3], bd);
            }
            #pragma unroll
            for (int mf = 0; mf < 2; mf++)
                #pragma unroll
                for (int nq = 0; nq < 4; nq++) {
                    mma16816(c[mf][nq * 2 + 0], a[mf], b[nq][0], b[nq][2]);
                    mma16816(c[mf][nq * 2 + 1], a[mf], b[nq][1], b[nq][3]);
                }
        }
        __syncthreads();
    }

    #pragma unroll
    for (int mf = 0; mf < 2; mf++) {
        #pragma unroll
        for (int nf = 0; nf < 8; nf++) {
            int row = bm * 128 + wm * 32 + mf * 16 + g;
            int col = bn * 128 + wn * 64 + nf * 8 + 2 * t4;
            float2 bbv = *(const float2*)(b2 + col);
            float2 v0 = make_float2(c[mf][nf][0] + bbv.x, c[mf][nf][1] + bbv.y);
            float2 v1 = make_float2(c[mf][nf][2] + bbv.x, c[mf][nf][3] + bbv.y);
            *(float2*)(out + (size_t)row * 512 + col) = v0;
            *(float2*)(out + (size_t)(row + 8) * 512 + col) = v1;
        }
    }
}

// ---------------- launch ----------------
extern "C" void kernel_launch(void* const* d_in, const int* in_sizes, int n_in,
                              void* d_out, int out_size)
{
    const float* xyzt  = (const float*)d_in[0];
    const int*   smask = (const int*)d_in[1];
    const int*   tmask = (const int*)d_in[2];
    const float* stab  = (const float*)d_in[3];
    const float* ttab  = (const float*)d_in[4];
    const float* w1    = (const float*)d_in[5];
    const float* b1    = (const float*)d_in[6];
    const float* lng   = (const float*)d_in[7];
    const float* lnb   = (const float*)d_in[8];
    const float* w2    = (const float*)d_in[9];
    const float* b2    = (const float*)d_in[10];
    float*       out   = (float*)d_out;

    cudaFuncSetAttribute(mlp1_kernel, cudaFuncAttributeMaxDynamicSharedMemorySize,
                         M1_SMEM_BYTES);
    cudaFuncSetAttribute(mlp2_kernel, cudaFuncAttributeMaxDynamicSharedMemorySize,
                         SMEM2_BYTES);

    dim3 tb(32, 32);
    dim3 tg(16, 16);
    prep_w2_kernel<<<tg, tb>>>(w2);
    prep_w1_kernel<<<(HIDDEN * DIM_IN) / 256, 256>>>(w1);
    encode_kernel<<<B_PTS / 256, 256>>>((const float4*)xyzt, smask, tmask,
                                        (const float2*)stab, (const float2*)ttab);
    mlp1_kernel<<<B_PTS / 32, 256, M1_SMEM_BYTES>>>(b1, lng, lnb);
    dim3 g2(HIDDEN / 128, B_PTS / 128);
    mlp2_kernel<<<g2, 256, SMEM2_BYTES>>>(b2, out);
}

// round 9
// speedup vs baseline: 2.2195x; 1.0074x over previous
#include <cuda_runtime.h>
#include <cuda_fp16.h>
#include <cstdint>
#include <math.h>

#define B_PTS   262144
#define HIDDEN  512
#define DIM_IN  48

// ---------------- scratch (static device arrays; no allocs) ----------------
__device__ __half g_feats[(size_t)B_PTS * DIM_IN];          // 24 MB fp16
__device__ __half g_h[(size_t)B_PTS * HIDDEN];              // 256 MB fp16
__device__ __half g_w2h[HIDDEN * HIDDEN];                   // [N][K] K-major fp16
__device__ __half g_w1h[HIDDEN * DIM_IN];                   // [N=512][K=48] fp16

__constant__ float c_sres[16] = {16,22,30,42,58,80,111,154,212,294,406,561,776,1072,1482,2048};
__constant__ float c_tres[8]  = {8,16,32,64,128,256,512,1024};

__device__ __forceinline__ void cp16(void* s, const void* g) {
    uint32_t sa = (uint32_t)__cvta_generic_to_shared(s);
    asm volatile("cp.async.cg.shared.global [%0], [%1], 16;" :: "r"(sa), "l"(g));
}
__device__ __forceinline__ void cp_commit() { asm volatile("cp.async.commit_group;"); }
template<int N> __device__ __forceinline__ void cp_wait() {
    asm volatile("cp.async.wait_group %0;" :: "n"(N));
}
__device__ __forceinline__ uint32_t smem_u32(const void* p) {
    return (uint32_t)__cvta_generic_to_shared(p);
}
__device__ __forceinline__ void ldsm_x4(uint32_t& r0, uint32_t& r1, uint32_t& r2, uint32_t& r3,
                                        uint32_t addr) {
    asm volatile("ldmatrix.sync.aligned.m8n8.x4.shared.b16 {%0,%1,%2,%3}, [%4];"
                 : "=r"(r0), "=r"(r1), "=r"(r2), "=r"(r3) : "r"(addr));
}
__device__ __forceinline__ void mma16816(float* c, const uint32_t* a, uint32_t b0, uint32_t b1) {
    asm volatile(
        "mma.sync.aligned.m16n8k16.row.col.f32.f16.f16.f32 "
        "{%0,%1,%2,%3},{%4,%5,%6,%7},{%8,%9},{%0,%1,%2,%3};"
        : "+f"(c[0]), "+f"(c[1]), "+f"(c[2]), "+f"(c[3])
        : "r"(a[0]), "r"(a[1]), "r"(a[2]), "r"(a[3]), "r"(b0), "r"(b1));
}
__device__ __forceinline__ float gelu_exact(float y) {
    return 0.5f * y * (1.0f + erff(y * 0.70710678118654752f));
}

// ---------------- kernel 0a: transpose + fp16-round w2 -> g_w2h[N][K] ----------------
__global__ void prep_w2_kernel(const float* __restrict__ w2) {
    __shared__ float tile[32][33];
    int x = blockIdx.x * 32 + threadIdx.x;   // n
    int y = blockIdx.y * 32 + threadIdx.y;   // k
    tile[threadIdx.y][threadIdx.x] = w2[y * 512 + x];
    __syncthreads();
    int ko = blockIdx.y * 32 + threadIdx.x;  // k
    int no = blockIdx.x * 32 + threadIdx.y;  // n
    g_w2h[no * 512 + ko] = __float2half_rn(tile[threadIdx.x][threadIdx.y]);
}

// ---------------- kernel 0b: transpose + fp16-round w1 -> g_w1h[N=512][K=48] ---------
__global__ void prep_w1_kernel(const float* __restrict__ w1) {
    int i = blockIdx.x * 256 + threadIdx.x;   // i over 512*48
    int n = i / 48, k = i % 48;
    g_w1h[i] = __float2half_rn(w1[k * 512 + n]);
}

// ---------------- kernel 1: 4D hash-grid encode -> fp16 feats ----------------
__global__ __launch_bounds__(256) void encode_kernel(
    const float4* __restrict__ xyzt,
    const int* __restrict__ smask,
    const int* __restrict__ tmask,
    const float2* __restrict__ stab,
    const float2* __restrict__ ttab)
{
    int i = blockIdx.x * 256 + threadIdx.x;
    float4 p = xyzt[i];
    float sm = smask[i] ? 1.0f : 0.0f;
    float tm = tmask[i] ? 1.0f : 0.0f;

    float out[DIM_IN];

    #pragma unroll
    for (int l = 0; l < 16; l++) {
        float r = c_sres[l];
        float px = p.x * r, py = p.y * r, pz = p.z * r;
        float fx = floorf(px), fy = floorf(py), fz = floorf(pz);
        unsigned bx = (unsigned)fx, by = (unsigned)fy, bz = (unsigned)fz;
        float wx1 = px - fx, wy1 = py - fy, wz1 = pz - fz;
        float wx0 = 1.0f - wx1, wy0 = 1.0f - wy1, wz0 = 1.0f - wz1;
        const float2* tab = stab + (size_t)l * 524288;
        unsigned hy0 = by * 2654435761u, hy1 = (by + 1u) * 2654435761u;
        unsigned hz0 = bz * 805459861u,  hz1 = (bz + 1u) * 805459861u;
        float f0 = 0.0f, f1 = 0.0f;
        #pragma unroll
        for (int cz = 0; cz < 2; cz++) {
            unsigned hz = cz ? hz1 : hz0; float wz = cz ? wz1 : wz0;
            #pragma unroll
            for (int cy = 0; cy < 2; cy++) {
                unsigned hy = cy ? hy1 : hy0; float wy = cy ? wy1 : wy0;
                #pragma unroll
                for (int cx = 0; cx < 2; cx++) {
                    unsigned idx = ((bx + (unsigned)cx) ^ hy ^ hz) & 524287u;
                    float w = (cx ? wx1 : wx0) * wy * wz;
                    float2 v = __ldg(tab + idx);
                    f0 += w * v.x;
                    f1 += w * v.y;
                }
            }
        }
        out[2 * l]     = f0 * sm;
        out[2 * l + 1] = f1 * sm;
    }

    #pragma unroll
    for (int l = 0; l < 8; l++) {
        float r = c_tres[l];
        float pt = p.w * r;
        float ft = floorf(pt);
        unsigned bt = (unsigned)ft;
        float w1v = pt - ft, w0v = 1.0f - w1v;
        const float2* tab = ttab + (size_t)l * 131072;
        float2 v0 = __ldg(tab + (bt & 131071u));
        float2 v1 = __ldg(tab + ((bt + 1u) & 131071u));
        out[32 + 2 * l]     = (w0v * v0.x + w1v * v1.x) * tm;
        out[32 + 2 * l + 1] = (w0v * v0.y + w1v * v1.y) * tm;
    }

    uint32_t w[24];
    #pragma unroll
    for (int j = 0; j < 24; j++) {
        __half2 h2 = __floats2half2_rn(out[2*j], out[2*j+1]);
        w[j] = *(uint32_t*)&h2;
    }
    uint4* dst = (uint4*)(g_feats + (size_t)i * DIM_IN);
    #pragma unroll
    for (int q = 0; q < 6; q++)
        dst[q] = make_uint4(w[4*q], w[4*q+1], w[4*q+2], w[4*q+3]);
}

// ---------------- kernel 2: GEMM1 (48->512) fp16 mma + LN + GELU -> fp16 h ----------
// CTA processes 256 rows as 8 sub-tiles of 32, loading w1s ONCE.
// 8 warps, one per 64-col slab. K=48 = 3 ksteps. Row stride 56 halves (conflict-free).
#define KP 56
#define ROWS_PER_CTA 256
#define SUBT 8
// smem: w1s 57344 | fs[2] 7168 | red 2048 | mus 128 | rss 128 | hstage 33280
#define M1_W1_OFF  0
#define M1_FS_OFF  57344
#define M1_RED_OFF 64512
#define M1_MUS_OFF 66560
#define M1_RSS_OFF 66688
#define M1_HST_OFF 66816
#define M1_SMEM_BYTES (66816 + 32 * 520 * 2)
__global__ __launch_bounds__(256, 2) void mlp1_kernel(
    const float* __restrict__ b1,
    const float* __restrict__ lng, const float* __restrict__ lnb)
{
    extern __shared__ __align__(16) char sm1[];
    __half* w1s = (__half*)(sm1 + M1_W1_OFF);    // [512][KP]
    __half* fs0 = (__half*)(sm1 + M1_FS_OFF);    // [2][32][KP]
    float2* red = (float2*)(sm1 + M1_RED_OFF);   // [32][8]
    float*  mus = (float*)(sm1 + M1_MUS_OFF);
    float*  rss = (float*)(sm1 + M1_RSS_OFF);
    __half* hstage = (__half*)(sm1 + M1_HST_OFF); // [32][520]

    int tid = threadIdx.x;
    int wid = tid >> 5, lane = tid & 31;
    const __half* fgbase = g_feats + (size_t)blockIdx.x * ROWS_PER_CTA * 48;

    // load w1h once: 512 rows x 6 chunks; each thread 2 rows x 6 chunks, no div
    {
        int r0 = tid * 2;
        #pragma unroll
        for (int rr = 0; rr < 2; rr++)
            #pragma unroll
            for (int cc = 0; cc < 6; cc++)
                cp16(w1s + (r0 + rr) * KP + cc * 8, g_w1h + (r0 + rr) * 48 + cc * 8);
    }
    // feats sub-tile 0
    if (tid < 192) {
        int r = tid / 6, cc = tid % 6;
        cp16(fs0 + r * KP + cc * 8, fgbase + r * 48 + cc * 8);
    }
    cp_commit();
    cp_wait<0>();
    __syncthreads();

    int g = lane >> 2, t4 = lane & 3;
    int lrow = lane & 15, lcol = (lane >> 4) * 8;
    uint32_t wsb = smem_u32(w1s);

    // per-thread invariant loads (same cols every sub-tile)
    float2 b1v[8], lgv[8], lbv[8];
    #pragma unroll
    for (int nf = 0; nf < 8; nf++) {
        int col = wid * 64 + nf * 8 + 2 * t4;
        b1v[nf] = *(const float2*)(b1 + col);
        lgv[nf] = *(const float2*)(lng + col);
        lbv[nf] = *(const float2*)(lnb + col);
    }

    // pre-load B fragments (w1) once: 3 ksteps x 4 nq x 4 regs = 48 regs
    uint32_t bfr[3][4][4];
    #pragma unroll
    for (int ks = 0; ks < 3; ks++)
        #pragma unroll
        for (int nq = 0; nq < 4; nq++) {
            uint32_t bd = wsb + (uint32_t)(((wid * 64 + nq * 16 + lrow) * KP + ks * 16 + lcol) * 2);
            ldsm_x4(bfr[ks][nq][0], bfr[ks][nq][1], bfr[ks][nq][2], bfr[ks][nq][3], bd);
        }

    for (int t = 0; t < SUBT; t++) {
        __half* fs = fs0 + (t & 1) * 32 * KP;
        uint32_t fsb = smem_u32(fs);

        // prefetch next feats sub-tile
        if (t + 1 < SUBT && tid < 192) {
            int r = tid / 6, cc = tid % 6;
            cp16(fs0 + ((t + 1) & 1) * 32 * KP + r * KP + cc * 8,
                 fgbase + (size_t)(t + 1) * 32 * 48 + r * 48 + cc * 8);
        }
        cp_commit();

        float c[2][8][4] = {};
        #pragma unroll
        for (int ks = 0; ks < 3; ks++) {
            uint32_t a[2][4];
            #pragma unroll
            for (int mf = 0; mf < 2; mf++) {
                uint32_t ad = fsb + (uint32_t)(((mf * 16 + lrow) * KP + ks * 16 + lcol) * 2);
                ldsm_x4(a[mf][0], a[mf][1], a[mf][2], a[mf][3], ad);
            }
            #pragma unroll
            for (int mf = 0; mf < 2; mf++)
                #pragma unroll
                for (int nq = 0; nq < 4; nq++) {
                    mma16816(c[mf][nq * 2 + 0], a[mf], bfr[ks][nq][0], bfr[ks][nq][2]);
                    mma16816(c[mf][nq * 2 + 1], a[mf], bfr[ks][nq][1], bfr[ks][nq][3]);
                }
        }

        // + b1
        #pragma unroll
        for (int nf = 0; nf < 8; nf++)
            #pragma unroll
            for (int mf = 0; mf < 2; mf++) {
                c[mf][nf][0] += b1v[nf].x; c[mf][nf][1] += b1v[nf].y;
                c[mf][nf][2] += b1v[nf].x; c[mf][nf][3] += b1v[nf].y;
            }

        // LN stats
        {
            float s[4] = {0,0,0,0}, s2[4] = {0,0,0,0};
            #pragma unroll
            for (int nf = 0; nf < 8; nf++)
                #pragma unroll
                for (int mf = 0; mf < 2; mf++) {
                    float v0 = c[mf][nf][0], v1 = c[mf][nf][1];
                    float v2 = c[mf][nf][2], v3 = c[mf][nf][3];
                    s[mf*2+0] += v0 + v1;  s2[mf*2+0] += v0*v0 + v1*v1;
                    s[mf*2+1] += v2 + v3;  s2[mf*2+1] += v2*v2 + v3*v3;
                }
            #pragma unroll
            for (int r = 0; r < 4; r++)
                #pragma unroll
                for (int off = 1; off < 4; off <<= 1) {
                    s[r]  += __shfl_xor_sync(0xffffffffu, s[r],  off);
                    s2[r] += __shfl_xor_sync(0xffffffffu, s2[r], off);
                }
            if (t4 == 0) {
                red[(g     ) * 8 + wid] = make_float2(s[0], s2[0]);
                red[(g + 8 ) * 8 + wid] = make_float2(s[1], s2[1]);
                red[(g + 16) * 8 + wid] = make_float2(s[2], s2[2]);
                red[(g + 24) * 8 + wid] = make_float2(s[3], s2[3]);
            }
        }
        __syncthreads();
        if (tid < 32) {
            float s = 0.0f, s2 = 0.0f;
            #pragma unroll
            for (int j = 0; j < 8; j++) {
                float2 v = red[tid * 8 + j];
                s += v.x; s2 += v.y;
            }
            float mu = s * (1.0f / 512.0f);
            float var = s2 * (1.0f / 512.0f) - mu * mu;
            mus[tid] = mu;
            rss[tid] = rsqrtf(var + 1e-5f);
        }
        __syncthreads();

        // epilogue: LN + GELU -> hstage
        {
            float mu[4], rs[4];
            #pragma unroll
            for (int r = 0; r < 4; r++) { mu[r] = mus[g + 8*r]; rs[r] = rss[g + 8*r]; }
            #pragma unroll
            for (int nf = 0; nf < 8; nf++) {
                int col = wid * 64 + nf * 8 + 2 * t4;
                #pragma unroll
                for (int mf = 0; mf < 2; mf++) {
                    int r0 = mf * 2, r1 = mf * 2 + 1;
                    float y0 = (c[mf][nf][0] - mu[r0]) * rs[r0] * lgv[nf].x + lbv[nf].x;
                    float y1 = (c[mf][nf][1] - mu[r0]) * rs[r0] * lgv[nf].y + lbv[nf].y;
                    float y2 = (c[mf][nf][2] - mu[r1]) * rs[r1] * lgv[nf].x + lbv[nf].x;
                    float y3 = (c[mf][nf][3] - mu[r1]) * rs[r1] * lgv[nf].y + lbv[nf].y;
                    __half2 h0 = __floats2half2_rn(gelu_exact(y0), gelu_exact(y1));
                    __half2 h1 = __floats2half2_rn(gelu_exact(y2), gelu_exact(y3));
                    *(__half2*)(hstage + (mf * 16 + g) * 520 + col)     = h0;
                    *(__half2*)(hstage + (mf * 16 + g + 8) * 520 + col) = h1;
                }
            }
        }
        __syncthreads();
        {
            uint4* hout = (uint4*)(g_h + ((size_t)blockIdx.x * ROWS_PER_CTA + t * 32) * 512);
            #pragma unroll
            for (int i = 0; i < 8; i++) {
                int q = tid + i * 256;
                int r = q >> 6, cc = q & 63;
                hout[q] = *(uint4*)(hstage + r * 520 + cc * 8);
            }
        }
        cp_wait<0>();
        __syncthreads();   // feats(t+1) visible; hstage/red free for reuse
    }
}

// ---------------- kernel 3: GEMM2 (512x512) fp16 mma.sync + ldmatrix ----------------
#define AST 40
#define STAGE_HALVES (2 * 128 * AST)
#define STAGE_BYTES  (STAGE_HALVES * 2)
#define SMEM2_BYTES  (3 * STAGE_BYTES)

__global__ __launch_bounds__(256, 2) void mlp2_kernel(
    const float* __restrict__ b2, float* __restrict__ out)
{
    extern __shared__ __half sm2[];
    uint32_t smem_base = smem_u32(sm2);

    int tid = threadIdx.x;
    int wid = tid >> 5, lane = tid & 31;
    int bn = blockIdx.x, bm = blockIdx.y;
    const __half* Ag = g_h   + (size_t)bm * 128 * 512;
    const __half* Bg = g_w2h + (size_t)bn * 128 * 512;

    auto load = [&](int kt, int s) {
        __half* dstA = sm2 + (size_t)s * STAGE_HALVES;
        #pragma unroll
        for (int i = 0; i < 2; i++) {
            int q = tid + i * 256;
            int r = q >> 2, cc = q & 3;
            cp16(dstA + r * AST + cc * 8, Ag + (size_t)r * 512 + kt * 32 + cc * 8);
        }
        __half* dstB = dstA + 128 * AST;
        #pragma unroll
        for (int i = 0; i < 2; i++) {
            int q = tid + i * 256;
            int r = q >> 2, cc = q & 3;
            cp16(dstB + r * AST + cc * 8, Bg + (size_t)r * 512 + kt * 32 + cc * 8);
        }
    };

    load(0, 0); cp_commit();
    load(1, 1); cp_commit();

    int wm = wid & 3, wn = wid >> 2;
    int g = lane >> 2, t4 = lane & 3;
    int lrow = lane & 15, lcol = (lane >> 4) * 8;

    float c[2][8][4] = {};

    for (int kt = 0; kt < 16; kt++) {
        if (kt < 15) cp_wait<1>(); else cp_wait<0>();
        __syncthreads();                       // stage kt visible; stage (kt+2)%3 free
        if (kt + 2 < 16) { load(kt + 2, (kt + 2) % 3); cp_commit(); }

        uint32_t base = smem_base + (uint32_t)((kt % 3) * STAGE_BYTES);

        #pragma unroll
        for (int ks = 0; ks < 2; ks++) {
            uint32_t a[2][4];
            #pragma unroll
            for (int mf = 0; mf < 2; mf++) {
                uint32_t ad = base + ((wm * 32 + mf * 16 + lrow) * AST + ks * 16 + lcol) * 2;
                ldsm_x4(a[mf][0], a[mf][1], a[mf][2], a[mf][3], ad);
            }
            uint32_t b[4][4];
            #pragma unroll
            for (int nq = 0; nq < 4; nq++) {
                uint32_t bd = base + 128 * AST * 2 +
                              ((wn * 64 + nq * 16 + lrow) * AST + ks * 16 + lcol) * 2;
                ldsm_x4(b[nq][0], b[nq][1], b[nq][2], b[nq][3], bd);
            }
            #pragma unroll
            for (int mf = 0; mf < 2; mf++)
                #pragma unroll
                for (int nq = 0; nq < 4; nq++) {
                    mma16816(c[mf][nq * 2 + 0], a[mf], b[nq][0], b[nq][2]);
                    mma16816(c[mf][nq * 2 + 1], a[mf], b[nq][1], b[nq][3]);
                }
        }
    }

    #pragma unroll
    for (int mf = 0; mf < 2; mf++) {
        #pragma unroll
        for (int nf = 0; nf < 8; nf++) {
            int row = bm * 128 + wm * 32 + mf * 16 + g;
            int col = bn * 128 + wn * 64 + nf * 8 + 2 * t4;
            float2 bbv = *(const float2*)(b2 + col);
            float2 v0 = make_float2(c[mf][nf][0] + bbv.x, c[mf][nf][1] + bbv.y);
            float2 v1 = make_float2(c[mf][nf][2] + bbv.x, c[mf][nf][3] + bbv.y);
            *(float2*)(out + (size_t)row * 512 + col) = v0;
            *(float2*)(out + (size_t)(row + 8) * 512 + col) = v1;
        }
    }
}

// ---------------- launch ----------------
extern "C" void kernel_launch(void* const* d_in, const int* in_sizes, int n_in,
                              void* d_out, int out_size)
{
    const float* xyzt  = (const float*)d_in[0];
    const int*   smask = (const int*)d_in[1];
    const int*   tmask = (const int*)d_in[2];
    const float* stab  = (const float*)d_in[3];
    const float* ttab  = (const float*)d_in[4];
    const float* w1    = (const float*)d_in[5];
    const float* b1    = (const float*)d_in[6];
    const float* lng   = (const float*)d_in[7];
    const float* lnb   = (const float*)d_in[8];
    const float* w2    = (const float*)d_in[9];
    const float* b2    = (const float*)d_in[10];
    float*       out   = (float*)d_out;

    cudaFuncSetAttribute(mlp1_kernel, cudaFuncAttributeMaxDynamicSharedMemorySize,
                         M1_SMEM_BYTES);
    cudaFuncSetAttribute(mlp2_kernel, cudaFuncAttributeMaxDynamicSharedMemorySize,
                         SMEM2_BYTES);

    dim3 tb(32, 32);
    dim3 tg(16, 16);
    prep_w2_kernel<<<tg, tb>>>(w2);
    prep_w1_kernel<<<(HIDDEN * DIM_IN) / 256, 256>>>(w1);
    encode_kernel<<<B_PTS / 256, 256>>>((const float4*)xyzt, smask, tmask,
                                        (const float2*)stab, (const float2*)ttab);
    mlp1_kernel<<<B_PTS / ROWS_PER_CTA, 256, M1_SMEM_BYTES>>>(b1, lng, lnb);
    dim3 g2(HIDDEN / 128, B_PTS / 128);
    mlp2_kernel<<<g2, 256, SMEM2_BYTES>>>(b2, out);
}